// round 4
// baseline (speedup 1.0000x reference)
#include <cuda_runtime.h>

#define NN   16384
#define NM   32
#define DIM  16
#define NR   64
#define NHOP 2
#define TOT  (NHOP*NN*NM)          // 1048576 slots

// ---- scratch (zero-init BSS; no runtime allocation) ----
__device__ int   g_cnt[NR];
__device__ int   g_cur[NR];
__device__ int   g_perm[TOT];      // packed: slot | (rid<<20)
__device__ float g_rh[TOT*DIM];    // 64 MB: Rh per slot, natural slot order

// ---------------- K0: zero counters ----------------
__global__ void k_zero() {
    if (threadIdx.x < NR) g_cnt[threadIdx.x] = 0;
}

// ---------------- K1: relation histogram ----------------
__global__ void k_hist(const int* __restrict__ mr) {
    __shared__ int sc[NR];
    if (threadIdx.x < NR) sc[threadIdx.x] = 0;
    __syncthreads();
    int stride = gridDim.x * blockDim.x;
    for (int i = blockIdx.x * blockDim.x + threadIdx.x; i < TOT; i += stride)
        atomicAdd(&sc[__ldg(mr + i)], 1);
    __syncthreads();
    if (threadIdx.x < NR) atomicAdd(&g_cnt[threadIdx.x], sc[threadIdx.x]);
}

// ---------------- K2: exclusive scan -> cursors ----------------
__global__ void k_scan() {
    if (threadIdx.x == 0) {
        int acc = 0;
        for (int r = 0; r < NR; r++) { g_cur[r] = acc; acc += g_cnt[r]; }
    }
}

// ---------------- K3: block-aggregated scatter (counting sort) ----------------
#define SCB     256
#define SCCHUNK 2048
__global__ __launch_bounds__(SCB)
void k_scatter(const int* __restrict__ mr) {
    __shared__ int scnt[NR];
    __shared__ int sbase[NR];
    int t = threadIdx.x;
    if (t < NR) scnt[t] = 0;
    __syncthreads();
    int start = blockIdx.x * SCCHUNK;
    int rids[SCCHUNK / SCB];
    #pragma unroll
    for (int k = 0; k < SCCHUNK / SCB; k++) {
        rids[k] = __ldg(mr + start + k * SCB + t);
        atomicAdd(&scnt[rids[k]], 1);
    }
    __syncthreads();
    if (t < NR) { sbase[t] = atomicAdd(&g_cur[t], scnt[t]); scnt[t] = 0; }
    __syncthreads();
    #pragma unroll
    for (int k = 0; k < SCCHUNK / SCB; k++) {
        int r   = rids[k];
        int pos = sbase[r] + atomicAdd(&scnt[r], 1);
        g_perm[pos] = (start + k * SCB + t) | (r << 20);
    }
}

// ---------------- K4: Rh = R @ h for every slot (relation-sorted) ----------------
// Warps see (almost always) a single rid -> R loads are uniform, L1-resident.
__global__ __launch_bounds__(256)
void k_rh(const int*   __restrict__ mh,
          const float* __restrict__ ent,
          const float* __restrict__ rel) {
    int j  = blockIdx.x * 256 + threadIdx.x;
    int pe = g_perm[j];
    int slot = pe & 0xFFFFF;
    int rid  = pe >> 20;

    int hid = __ldg(mh + slot);
    const float4* hp = reinterpret_cast<const float4*>(ent) + (size_t)hid * 4;
    float4 h0 = __ldg(hp + 0), h1 = __ldg(hp + 1), h2 = __ldg(hp + 2), h3 = __ldg(hp + 3);

    const float4* R4 = reinterpret_cast<const float4*>(rel) + (size_t)rid * 64;
    float rh[16];
    #pragma unroll
    for (int d = 0; d < 16; d++) {
        float4 a = __ldg(R4 + d * 4 + 0);
        float4 b = __ldg(R4 + d * 4 + 1);
        float4 c = __ldg(R4 + d * 4 + 2);
        float4 e = __ldg(R4 + d * 4 + 3);
        float acc = a.x * h0.x;
        acc = fmaf(a.y, h0.y, acc); acc = fmaf(a.z, h0.z, acc); acc = fmaf(a.w, h0.w, acc);
        acc = fmaf(b.x, h1.x, acc); acc = fmaf(b.y, h1.y, acc);
        acc = fmaf(b.z, h1.z, acc); acc = fmaf(b.w, h1.w, acc);
        acc = fmaf(c.x, h2.x, acc); acc = fmaf(c.y, h2.y, acc);
        acc = fmaf(c.z, h2.z, acc); acc = fmaf(c.w, h2.w, acc);
        acc = fmaf(e.x, h3.x, acc); acc = fmaf(e.y, h3.y, acc);
        acc = fmaf(e.z, h3.z, acc); acc = fmaf(e.w, h3.w, acc);
        rh[d] = acc;
    }
    float4* dst = reinterpret_cast<float4*>(g_rh) + (size_t)slot * 4;
    dst[0] = make_float4(rh[0],  rh[1],  rh[2],  rh[3]);
    dst[1] = make_float4(rh[4],  rh[5],  rh[6],  rh[7]);
    dst[2] = make_float4(rh[8],  rh[9],  rh[10], rh[11]);
    dst[3] = make_float4(rh[12], rh[13], rh[14], rh[15]);
}

// ---------------- K5: scores, softmax, weighted tails, item update ----------------
// One warp per node. Chunked layout: lane = (quad q = lane>>2, chunk c = lane&3).
__global__ __launch_bounds__(256)
void k_final(const int*   __restrict__ nodes,
             const int*   __restrict__ mt,
             const float* __restrict__ ent,
             const float* __restrict__ W,
             float*       __restrict__ out) {
    const unsigned F = 0xffffffffu;
    int lane = threadIdx.x & 31;
    int gw   = (blockIdx.x * blockDim.x + threadIdx.x) >> 5;
    int nw   = (gridDim.x * blockDim.x) >> 5;
    int myd  = lane & 15;
    int c    = lane & 3;
    int q    = lane >> 2;
    int qb   = lane & 28;

    // W row for this lane's output dim, cached in registers (amortized over nodes)
    float wrow[16];
    {
        const float4* wp = reinterpret_cast<const float4*>(W) + myd * 4;
        #pragma unroll
        for (int j = 0; j < 4; j++) {
            float4 v = __ldg(wp + j);
            wrow[4*j+0] = v.x; wrow[4*j+1] = v.y; wrow[4*j+2] = v.z; wrow[4*j+3] = v.w;
        }
    }

    for (int n = gw; n < NN; n += nw) {
        // item embedding, replicated (uniform loads)
        float it[16];
        {
            const float4* p = reinterpret_cast<const float4*>(ent) + (size_t)__ldg(nodes + n) * 4;
            #pragma unroll
            for (int j = 0; j < 4; j++) {
                float4 v = __ldg(p + j);
                it[4*j+0] = v.x; it[4*j+1] = v.y; it[4*j+2] = v.z; it[4*j+3] = v.w;
            }
        }

        float res = 0.f;
        #pragma unroll
        for (int hop = 0; hop < NHOP; hop++) {
            int sbase = (hop * NN + n) * NM;

            // ---- scores: fully coalesced Rh reads ----
            float p[4];
            {
                const float4* rp = reinterpret_cast<const float4*>(g_rh) + (size_t)sbase * 4;
                float s[4];
                #pragma unroll
                for (int k = 0; k < 4; k++) {
                    float4 v = __ldg(rp + k * 32 + lane);     // mem = 8k+q, chunk c
                    float pd = v.x * it[4*c+0];
                    pd = fmaf(v.y, it[4*c+1], pd);
                    pd = fmaf(v.z, it[4*c+2], pd);
                    pd = fmaf(v.w, it[4*c+3], pd);
                    pd += __shfl_xor_sync(F, pd, 1);
                    pd += __shfl_xor_sync(F, pd, 2);
                    s[k] = pd;                                 // score of memory 8k+q
                }
                float mx = fmaxf(fmaxf(s[0], s[1]), fmaxf(s[2], s[3]));
                mx = fmaxf(mx, __shfl_xor_sync(F, mx, 4));
                mx = fmaxf(mx, __shfl_xor_sync(F, mx, 8));
                mx = fmaxf(mx, __shfl_xor_sync(F, mx, 16));
                float e0 = __expf(s[0] - mx), e1 = __expf(s[1] - mx);
                float e2 = __expf(s[2] - mx), e3 = __expf(s[3] - mx);
                float ls = e0 + e1 + e2 + e3;
                ls += __shfl_xor_sync(F, ls, 4);
                ls += __shfl_xor_sync(F, ls, 8);
                ls += __shfl_xor_sync(F, ls, 16);
                float inv = 1.f / ls;
                p[0] = e0 * inv; p[1] = e1 * inv; p[2] = e2 * inv; p[3] = e3 * inv;
            }

            // ---- o = sum p_m * t_m, quad-cooperative t loads ----
            float ox = 0.f, oy = 0.f, oz = 0.f, ow = 0.f;
            #pragma unroll
            for (int k = 0; k < 4; k++) {
                int m   = 8 * k + q;
                int tid = __ldg(mt + sbase + m);               // quad-uniform, 1 line/warp
                float4 tv = __ldg(reinterpret_cast<const float4*>(ent) + (size_t)tid * 4 + c);
                ox = fmaf(p[k], tv.x, ox); oy = fmaf(p[k], tv.y, oy);
                oz = fmaf(p[k], tv.z, oz); ow = fmaf(p[k], tv.w, ow);
            }
            #pragma unroll
            for (int st = 4; st <= 16; st <<= 1) {
                ox += __shfl_xor_sync(F, ox, st);
                oy += __shfl_xor_sync(F, oy, st);
                oz += __shfl_xor_sync(F, oz, st);
                ow += __shfl_xor_sync(F, ow, st);
            }
            // assemble full o[16] (source lane qb+cc holds chunk cc)
            float o[16];
            #pragma unroll
            for (int cc = 0; cc < 4; cc++) {
                o[4*cc+0] = __shfl_sync(F, ox, qb + cc);
                o[4*cc+1] = __shfl_sync(F, oy, qb + cc);
                o[4*cc+2] = __shfl_sync(F, oz, qb + cc);
                o[4*cc+3] = __shfl_sync(F, ow, qb + cc);
            }

            if (hop == 0) {
                res = 2.f * o[myd];
                float nd = 0.f;
                #pragma unroll
                for (int e = 0; e < 16; e++) nd = fmaf(it[e] + o[e], wrow[e], nd);
                #pragma unroll
                for (int e = 0; e < 16; e++) it[e] = __shfl_sync(F, nd, e);
            } else {
                res += o[myd];
            }
        }
        if (lane < 16) out[n * DIM + lane] = res;
    }
}

extern "C" void kernel_launch(void* const* d_in, const int* in_sizes, int n_in,
                              void* d_out, int out_size)
{
    const int*   nodes = (const int*)  d_in[0];
    const int*   mh    = (const int*)  d_in[1];
    const int*   mr    = (const int*)  d_in[2];
    const int*   mt    = (const int*)  d_in[3];
    const float* ent   = (const float*)d_in[4];
    const float* rel   = (const float*)d_in[5];
    const float* W     = (const float*)d_in[6];
    float*       out   = (float*)      d_out;

    k_zero   <<<1, 64>>>();
    k_hist   <<<256, 256>>>(mr);
    k_scan   <<<1, 32>>>();
    k_scatter<<<TOT / SCCHUNK, SCB>>>(mr);
    k_rh     <<<TOT / 256, 256>>>(mh, ent, rel);
    k_final  <<<512, 256>>>(nodes, mt, ent, W, out);
}

// round 7
// speedup vs baseline: 1.1091x; 1.1091x over previous
#include <cuda_runtime.h>

#define NN   16384
#define NM   32
#define DIM  16
#define NR   64
#define PAD  260      // floats per relation in smem; 4*rid mod 32 spreads quads across banks

__global__ __launch_bounds__(256)
void ripple_kernel(const int*   __restrict__ nodes,
                   const int*   __restrict__ mh,
                   const int*   __restrict__ mr,
                   const int*   __restrict__ mt,
                   const float* __restrict__ ent,
                   const float* __restrict__ rel,
                   const float* __restrict__ W,
                   float*       __restrict__ out)
{
    extern __shared__ float sh[];   // relation table, column-major + chunk-swizzled

    // Stage relations: R[d][e] of rid -> sh[rid*PAD + e*16 + ((d>>2)^(e>>2))*4 + (d&3)]
    for (int i = threadIdx.x; i < NR * 256; i += blockDim.x) {
        int rid = i >> 8, rem = i & 255;
        int d = rem >> 4, e = rem & 15;
        sh[rid * PAD + e * 16 + (((d >> 2) ^ (e >> 2)) & 3) * 4 + (d & 3)] = rel[i];
    }
    __syncthreads();

    const unsigned F = 0xffffffffu;
    const int lane = threadIdx.x & 31;
    const int gw   = (blockIdx.x * blockDim.x + threadIdx.x) >> 5;
    const int nw   = (gridDim.x * blockDim.x) >> 5;
    const int c    = lane & 3;        // chunk within quad
    const int qd   = lane >> 2;       // quad id (0..7)
    const int qb   = lane & 28;       // quad base lane
    const int myd  = lane & 15;       // this lane's output dim

    // W row for this lane's dim, cached in registers
    float wrow[16];
    {
        const float4* wp = reinterpret_cast<const float4*>(W) + myd * 4;
        #pragma unroll
        for (int j = 0; j < 4; j++) {
            float4 v = __ldg(wp + j);
            wrow[4*j+0] = v.x; wrow[4*j+1] = v.y; wrow[4*j+2] = v.z; wrow[4*j+3] = v.w;
        }
    }

    const float4* ent4 = reinterpret_cast<const float4*>(ent);

    for (int n = gw; n < NN; n += nw) {
        // item embedding, replicated across lanes (uniform loads)
        float it[16];
        {
            const float4* p = ent4 + (size_t)__ldg(nodes + n) * 4;
            #pragma unroll
            for (int j = 0; j < 4; j++) {
                float4 v = __ldg(p + j);
                it[4*j+0] = v.x; it[4*j+1] = v.y; it[4*j+2] = v.z; it[4*j+3] = v.w;
            }
        }

        float res = 0.f;

        #pragma unroll
        for (int hop = 0; hop < 2; hop++) {
            const int sbase = (hop * NN + n) * NM;

            // ---- scores: quad qd handles slot m = 8r+qd at round r ----
            float s[4];
            #pragma unroll
            for (int r = 0; r < 4; r++) {
                const int m   = 8 * r + qd;
                const int hid = __ldg(mh + sbase + m);      // quad-uniform -> 1 line
                const int rid = __ldg(mr + sbase + m);
                float4 hv = __ldg(ent4 + (size_t)hid * 4 + c);   // chunk c of h

                const float* rb = sh + rid * PAD;
                float sp = 0.f;
                #pragma unroll
                for (int j = 0; j < 4; j++) {               // lane's columns e=4c+j
                    const int e = 4 * c + j;
                    float colacc = 0.f;
                    #pragma unroll
                    for (int dq = 0; dq < 4; dq++) {        // logical d-chunk
                        const int phys = dq ^ c;            // swizzle
                        float4 v = *reinterpret_cast<const float4*>(rb + e * 16 + phys * 4);
                        colacc = fmaf(v.x, it[4*dq+0], colacc);
                        colacc = fmaf(v.y, it[4*dq+1], colacc);
                        colacc = fmaf(v.z, it[4*dq+2], colacc);
                        colacc = fmaf(v.w, it[4*dq+3], colacc);
                    }
                    const float he = (j == 0) ? hv.x : (j == 1) ? hv.y : (j == 2) ? hv.z : hv.w;
                    sp = fmaf(colacc, he, sp);
                }
                // intra-quad reduce -> all 4 lanes hold score of slot m
                sp += __shfl_xor_sync(F, sp, 1);
                sp += __shfl_xor_sync(F, sp, 2);
                s[r] = sp;
            }

            // ---- softmax over 32 slots (4 local + butterfly over quads) ----
            float p[4];
            {
                float mx = fmaxf(fmaxf(s[0], s[1]), fmaxf(s[2], s[3]));
                mx = fmaxf(mx, __shfl_xor_sync(F, mx, 4));
                mx = fmaxf(mx, __shfl_xor_sync(F, mx, 8));
                mx = fmaxf(mx, __shfl_xor_sync(F, mx, 16));
                float e0 = __expf(s[0] - mx), e1 = __expf(s[1] - mx);
                float e2 = __expf(s[2] - mx), e3 = __expf(s[3] - mx);
                float ls = e0 + e1 + e2 + e3;
                ls += __shfl_xor_sync(F, ls, 4);
                ls += __shfl_xor_sync(F, ls, 8);
                ls += __shfl_xor_sync(F, ls, 16);
                float inv = 1.f / ls;
                p[0] = e0 * inv; p[1] = e1 * inv; p[2] = e2 * inv; p[3] = e3 * inv;
            }

            // ---- o = sum p_m * t_m (quad-cooperative t loads) ----
            float ox = 0.f, oy = 0.f, oz = 0.f, ow = 0.f;
            #pragma unroll
            for (int r = 0; r < 4; r++) {
                const int m   = 8 * r + qd;
                const int tid = __ldg(mt + sbase + m);      // quad-uniform
                float4 tv = __ldg(ent4 + (size_t)tid * 4 + c);
                ox = fmaf(p[r], tv.x, ox); oy = fmaf(p[r], tv.y, oy);
                oz = fmaf(p[r], tv.z, oz); ow = fmaf(p[r], tv.w, ow);
            }
            #pragma unroll
            for (int st = 4; st <= 16; st <<= 1) {
                ox += __shfl_xor_sync(F, ox, st);
                oy += __shfl_xor_sync(F, oy, st);
                oz += __shfl_xor_sync(F, oz, st);
                ow += __shfl_xor_sync(F, ow, st);
            }
            // now every lane holds full chunk-c of o

            if (hop == 0) {
                // assemble full o[16]
                float o[16];
                #pragma unroll
                for (int cc = 0; cc < 4; cc++) {
                    o[4*cc+0] = __shfl_sync(F, ox, qb + cc);
                    o[4*cc+1] = __shfl_sync(F, oy, qb + cc);
                    o[4*cc+2] = __shfl_sync(F, oz, qb + cc);
                    o[4*cc+3] = __shfl_sync(F, ow, qb + cc);
                }
                res = 2.f * o[myd];
                // item = (item + o) @ W.T
                float nd = 0.f;
                #pragma unroll
                for (int e = 0; e < 16; e++) nd = fmaf(it[e] + o[e], wrow[e], nd);
                #pragma unroll
                for (int e = 0; e < 16; e++) it[e] = __shfl_sync(F, nd, e);
            } else {
                // only need o[myd]: fetch chunk myd>>2 from own quad row, select component
                const int src = qb + (myd >> 2);
                float t0 = __shfl_sync(F, ox, src);
                float t1 = __shfl_sync(F, oy, src);
                float t2 = __shfl_sync(F, oz, src);
                float t3 = __shfl_sync(F, ow, src);
                const int comp = myd & 3;
                float oval = (comp == 0) ? t0 : (comp == 1) ? t1 : (comp == 2) ? t2 : t3;
                res += oval;
            }
        }

        if (lane < 16) out[n * DIM + lane] = res;
    }
}

extern "C" void kernel_launch(void* const* d_in, const int* in_sizes, int n_in,
                              void* d_out, int out_size)
{
    const int*   nodes = (const int*)  d_in[0];
    const int*   mh    = (const int*)  d_in[1];
    const int*   mr    = (const int*)  d_in[2];
    const int*   mt    = (const int*)  d_in[3];
    const float* ent   = (const float*)d_in[4];
    const float* rel   = (const float*)d_in[5];
    const float* W     = (const float*)d_in[6];
    float*       out   = (float*)      d_out;

    const int smem = NR * PAD * sizeof(float);   // 66560 B
    cudaFuncSetAttribute(ripple_kernel, cudaFuncAttributeMaxDynamicSharedMemorySize, smem);

    ripple_kernel<<<148 * 3, 256, smem>>>(nodes, mh, mr, mt, ent, rel, W, out);
}

// round 8
// speedup vs baseline: 1.4442x; 1.3021x over previous
#include <cuda_runtime.h>

#define NN   16384
#define NM   32
#define DIM  16
#define NR   64
#define PAD  260      // floats per relation in smem; 4*rid mod 32 spreads quads across banks
#define WPAD 17       // 17*d mod 32 distinct for d=0..15 -> conflict-free W rows

__global__ __launch_bounds__(256, 3)
void ripple_kernel(const int*   __restrict__ nodes,
                   const int*   __restrict__ mh,
                   const int*   __restrict__ mr,
                   const int*   __restrict__ mt,
                   const float* __restrict__ ent,
                   const float* __restrict__ rel,
                   const float* __restrict__ W,
                   float*       __restrict__ out)
{
    extern __shared__ float sh[];   // relation table (swizzled) + W (padded)
    float* shW = sh + NR * PAD;

    // Stage relations: R[d][e] of rid -> sh[rid*PAD + e*16 + ((d>>2)^(e>>2))*4 + (d&3)]
    for (int i = threadIdx.x; i < NR * 256; i += blockDim.x) {
        int rid = i >> 8, rem = i & 255;
        int d = rem >> 4, e = rem & 15;
        sh[rid * PAD + e * 16 + (((d >> 2) ^ (e >> 2)) & 3) * 4 + (d & 3)] = rel[i];
    }
    // Stage W rows (padded, conflict-free reads)
    for (int i = threadIdx.x; i < 256; i += blockDim.x) {
        int d = i >> 4, e = i & 15;
        shW[d * WPAD + e] = W[i];
    }
    __syncthreads();

    const unsigned F = 0xffffffffu;
    const int lane = threadIdx.x & 31;
    const int gw   = (blockIdx.x * blockDim.x + threadIdx.x) >> 5;
    const int nw   = (gridDim.x * blockDim.x) >> 5;
    const int c    = lane & 3;        // chunk within quad
    const int qd   = lane >> 2;       // quad id (0..7)
    const int qb   = lane & 28;       // quad base lane
    const int myd  = lane & 15;       // this lane's output dim

    const float4* ent4 = reinterpret_cast<const float4*>(ent);

    for (int n = gw; n < NN; n += nw) {
        // item embedding, replicated across lanes (uniform loads)
        float it[16];
        {
            const float4* p = ent4 + (size_t)__ldg(nodes + n) * 4;
            #pragma unroll
            for (int j = 0; j < 4; j++) {
                float4 v = __ldg(p + j);
                it[4*j+0] = v.x; it[4*j+1] = v.y; it[4*j+2] = v.z; it[4*j+3] = v.w;
            }
        }

        float res = 0.f;

        #pragma unroll
        for (int hop = 0; hop < 2; hop++) {
            const int sbase = (hop * NN + n) * NM;

            // ---- scores: quad qd handles slot m = 8r+qd at round r ----
            float s[4];
            #pragma unroll
            for (int r = 0; r < 4; r++) {
                const int m   = 8 * r + qd;
                const int hid = __ldg(mh + sbase + m);      // quad-uniform -> 1 line
                const int rid = __ldg(mr + sbase + m);
                float4 hv = __ldg(ent4 + (size_t)hid * 4 + c);   // chunk c of h

                const float* rb = sh + rid * PAD;
                float sp = 0.f;
                #pragma unroll
                for (int j = 0; j < 4; j++) {               // lane's columns e=4c+j
                    const int e = 4 * c + j;
                    float colacc = 0.f;
                    #pragma unroll
                    for (int dq = 0; dq < 4; dq++) {        // logical d-chunk
                        const int phys = dq ^ c;            // swizzle
                        float4 v = *reinterpret_cast<const float4*>(rb + e * 16 + phys * 4);
                        colacc = fmaf(v.x, it[4*dq+0], colacc);
                        colacc = fmaf(v.y, it[4*dq+1], colacc);
                        colacc = fmaf(v.z, it[4*dq+2], colacc);
                        colacc = fmaf(v.w, it[4*dq+3], colacc);
                    }
                    const float he = (j == 0) ? hv.x : (j == 1) ? hv.y : (j == 2) ? hv.z : hv.w;
                    sp = fmaf(colacc, he, sp);
                }
                // intra-quad reduce -> all 4 lanes hold score of slot m
                sp += __shfl_xor_sync(F, sp, 1);
                sp += __shfl_xor_sync(F, sp, 2);
                s[r] = sp;
            }

            // ---- softmax over 32 slots (4 local + butterfly over quads) ----
            float p[4];
            {
                float mx = fmaxf(fmaxf(s[0], s[1]), fmaxf(s[2], s[3]));
                mx = fmaxf(mx, __shfl_xor_sync(F, mx, 4));
                mx = fmaxf(mx, __shfl_xor_sync(F, mx, 8));
                mx = fmaxf(mx, __shfl_xor_sync(F, mx, 16));
                float e0 = __expf(s[0] - mx), e1 = __expf(s[1] - mx);
                float e2 = __expf(s[2] - mx), e3 = __expf(s[3] - mx);
                float ls = e0 + e1 + e2 + e3;
                ls += __shfl_xor_sync(F, ls, 4);
                ls += __shfl_xor_sync(F, ls, 8);
                ls += __shfl_xor_sync(F, ls, 16);
                float inv = 1.f / ls;
                p[0] = e0 * inv; p[1] = e1 * inv; p[2] = e2 * inv; p[3] = e3 * inv;
            }

            // ---- o = sum p_m * t_m (quad-cooperative t loads) ----
            float ox = 0.f, oy = 0.f, oz = 0.f, ow = 0.f;
            #pragma unroll
            for (int r = 0; r < 4; r++) {
                const int m   = 8 * r + qd;
                const int tid = __ldg(mt + sbase + m);      // quad-uniform
                float4 tv = __ldg(ent4 + (size_t)tid * 4 + c);
                ox = fmaf(p[r], tv.x, ox); oy = fmaf(p[r], tv.y, oy);
                oz = fmaf(p[r], tv.z, oz); ow = fmaf(p[r], tv.w, ow);
            }
            #pragma unroll
            for (int st = 4; st <= 16; st <<= 1) {
                ox += __shfl_xor_sync(F, ox, st);
                oy += __shfl_xor_sync(F, oy, st);
                oz += __shfl_xor_sync(F, oz, st);
                ow += __shfl_xor_sync(F, ow, st);
            }
            // now every lane holds full chunk-c of o

            if (hop == 0) {
                // assemble full o[16]
                float o[16];
                #pragma unroll
                for (int cc = 0; cc < 4; cc++) {
                    o[4*cc+0] = __shfl_sync(F, ox, qb + cc);
                    o[4*cc+1] = __shfl_sync(F, oy, qb + cc);
                    o[4*cc+2] = __shfl_sync(F, oz, qb + cc);
                    o[4*cc+3] = __shfl_sync(F, ow, qb + cc);
                }
                res = 2.f * o[myd];
                // item = (item + o) @ W.T   (W row from conflict-free smem)
                const float* wr = shW + myd * WPAD;
                float nd = 0.f;
                #pragma unroll
                for (int e = 0; e < 16; e++) nd = fmaf(it[e] + o[e], wr[e], nd);
                #pragma unroll
                for (int e = 0; e < 16; e++) it[e] = __shfl_sync(F, nd, e);
            } else {
                // only need o[myd]: fetch chunk myd>>2 from own quad row, select component
                const int src = qb + (myd >> 2);
                float t0 = __shfl_sync(F, ox, src);
                float t1 = __shfl_sync(F, oy, src);
                float t2 = __shfl_sync(F, oz, src);
                float t3 = __shfl_sync(F, ow, src);
                const int comp = myd & 3;
                float oval = (comp == 0) ? t0 : (comp == 1) ? t1 : (comp == 2) ? t2 : t3;
                res += oval;
            }
        }

        if (lane < 16) out[n * DIM + lane] = res;
    }
}

extern "C" void kernel_launch(void* const* d_in, const int* in_sizes, int n_in,
                              void* d_out, int out_size)
{
    const int*   nodes = (const int*)  d_in[0];
    const int*   mh    = (const int*)  d_in[1];
    const int*   mr    = (const int*)  d_in[2];
    const int*   mt    = (const int*)  d_in[3];
    const float* ent   = (const float*)d_in[4];
    const float* rel   = (const float*)d_in[5];
    const float* W     = (const float*)d_in[6];
    float*       out   = (float*)      d_out;

    const int smem = (NR * PAD + 16 * WPAD) * sizeof(float);   // 67648 B; 3 blocks/SM fits
    cudaFuncSetAttribute(ripple_kernel, cudaFuncAttributeMaxDynamicSharedMemorySize, smem);

    ripple_kernel<<<148 * 3, 256, smem>>>(nodes, mh, mr, mt, ent, rel, W, out);
}

// round 10
// speedup vs baseline: 2.2624x; 1.5665x over previous
#include <cuda_runtime.h>
#include <cuda_fp16.h>

#define NN   16384
#define NM   32
#define DIM  16
#define NR   64
#define WPAD 17      // 17*d mod 32 distinct for d=0..15 -> conflict-free W rows

// Shared layout: [0, 8192) uint32 words = fp16 R table (64 rel x 256 halves, identity order)
//                then W padded rows (16 x 17 floats)
#define R_WORDS (NR * 128)

__global__ __launch_bounds__(256, 3)
void ripple_kernel(const int*   __restrict__ nodes,
                   const int*   __restrict__ mh,
                   const int*   __restrict__ mr,
                   const int*   __restrict__ mt,
                   const float* __restrict__ ent,
                   const float* __restrict__ rel,
                   const float* __restrict__ W,
                   float*       __restrict__ out)
{
    extern __shared__ unsigned int shm[];
    float* shW = reinterpret_cast<float*>(shm + R_WORDS);

    // Stage R as fp16 (identity layout: half index = rid*256 + d*16 + e)
    {
        const float4* rel4 = reinterpret_cast<const float4*>(rel);
        for (int i = threadIdx.x; i < NR * 64; i += blockDim.x) {
            float4 v = rel4[i];
            __half2 a = __floats2half2_rn(v.x, v.y);
            __half2 b = __floats2half2_rn(v.z, v.w);
            shm[2*i]   = *reinterpret_cast<unsigned int*>(&a);
            shm[2*i+1] = *reinterpret_cast<unsigned int*>(&b);
        }
    }
    for (int i = threadIdx.x; i < 256; i += blockDim.x)
        shW[(i >> 4) * WPAD + (i & 15)] = W[i];
    __syncthreads();

    const unsigned F = 0xffffffffu;
    const int lane = threadIdx.x & 31;
    const int gw   = (blockIdx.x * blockDim.x + threadIdx.x) >> 5;
    const int nw   = (gridDim.x * blockDim.x) >> 5;
    const int g    = lane >> 3;        // octet id (0..3)
    const int k    = lane & 7;         // position within octet
    const int kh   = k & 1;            // which half of h this lane consumes (scores)
    const int kc   = k & 3;            // t chunk this lane accumulates
    const int khalf= k >> 2;           // r-range half for tail accumulation (0/1)
    const int k2   = k >> 1;           // d-offset selector (0..3)
    const int myd  = lane & 15;

    const float4* ent4 = reinterpret_cast<const float4*>(ent);
    const uint4*  shR4 = reinterpret_cast<const uint4*>(shm);

    for (int n = gw; n < NN; n += nw) {
        float it[16];
        {
            const float4* p = ent4 + (size_t)__ldg(nodes + n) * 4;
            #pragma unroll
            for (int j = 0; j < 4; j++) {
                float4 v = __ldg(p + j);
                it[4*j+0] = v.x; it[4*j+1] = v.y; it[4*j+2] = v.z; it[4*j+3] = v.w;
            }
        }

        float res = 0.f;

        #pragma unroll
        for (int hop = 0; hop < 2; hop++) {
            const int sbase = (hop * NN + n) * NM;

            // item value this lane needs per j: it[4j + k2]
            float itp[4];
            #pragma unroll
            for (int j = 0; j < 4; j++) {
                itp[j] = (k2 == 0) ? it[4*j] : (k2 == 1) ? it[4*j+1]
                       : (k2 == 2) ? it[4*j+2] : it[4*j+3];
            }

            // ---- scores: octet g handles slot m = 4r+g; R reads conflict-free ----
            float s[8];
            #pragma unroll
            for (int r = 0; r < 8; r++) {
                const int m   = 4 * r + g;
                const int hid = __ldg(mh + sbase + m);        // octet-uniform
                const int rid = __ldg(mr + sbase + m);
                float4 ha = __ldg(ent4 + (size_t)hid * 4 + 2 * kh);
                float4 hb = __ldg(ent4 + (size_t)hid * 4 + 2 * kh + 1);

                const uint4* rb = shR4 + rid * 32 + k;        // word rid*128 + 4k
                float sp = 0.f;
                #pragma unroll
                for (int j = 0; j < 4; j++) {                 // d = 4j + k2
                    uint4 w = rb[8 * j];                      // banks 4k..4k+3: conflict-free
                    float2 f0 = __half22float2(*reinterpret_cast<__half2*>(&w.x));
                    float2 f1 = __half22float2(*reinterpret_cast<__half2*>(&w.y));
                    float2 f2 = __half22float2(*reinterpret_cast<__half2*>(&w.z));
                    float2 f3 = __half22float2(*reinterpret_cast<__half2*>(&w.w));
                    float inner = f0.x * ha.x;
                    inner = fmaf(f0.y, ha.y, inner);
                    inner = fmaf(f1.x, ha.z, inner);
                    inner = fmaf(f1.y, ha.w, inner);
                    inner = fmaf(f2.x, hb.x, inner);
                    inner = fmaf(f2.y, hb.y, inner);
                    inner = fmaf(f3.x, hb.z, inner);
                    inner = fmaf(f3.y, hb.w, inner);
                    sp = fmaf(itp[j], inner, sp);
                }
                sp += __shfl_xor_sync(F, sp, 1);
                sp += __shfl_xor_sync(F, sp, 2);
                sp += __shfl_xor_sync(F, sp, 4);
                s[r] = sp;                                    // score of slot 4r+g
            }

            // ---- softmax over 32 slots (8 local + butterfly across octets) ----
            float p[8];
            {
                float mx = s[0];
                #pragma unroll
                for (int r = 1; r < 8; r++) mx = fmaxf(mx, s[r]);
                mx = fmaxf(mx, __shfl_xor_sync(F, mx, 8));
                mx = fmaxf(mx, __shfl_xor_sync(F, mx, 16));
                float ls = 0.f;
                #pragma unroll
                for (int r = 0; r < 8; r++) { p[r] = __expf(s[r] - mx); ls += p[r]; }
                ls += __shfl_xor_sync(F, ls, 8);
                ls += __shfl_xor_sync(F, ls, 16);
                float inv = 1.f / ls;
                #pragma unroll
                for (int r = 0; r < 8; r++) p[r] *= inv;
            }

            // ---- o = sum p_m * t_m ----
            // Lane handles chunk kc of slots r in its half (khalf): r = 4*khalf + rr.
            // Disjoint halves -> stride-4 shfl combines them; strides 8,16 combine octets.
            float ox = 0.f, oy = 0.f, oz = 0.f, ow = 0.f;
            #pragma unroll
            for (int rr = 0; rr < 4; rr++) {
                const int r   = 4 * khalf + rr;
                const int tid = __ldg(mt + sbase + 4 * r + g);
                float4 tv = __ldg(ent4 + (size_t)tid * 4 + kc);
                ox = fmaf(p[r], tv.x, ox); oy = fmaf(p[r], tv.y, oy);
                oz = fmaf(p[r], tv.z, oz); ow = fmaf(p[r], tv.w, ow);
            }
            #pragma unroll
            for (int st = 4; st <= 16; st <<= 1) {
                ox += __shfl_xor_sync(F, ox, st);
                oy += __shfl_xor_sync(F, oy, st);
                oz += __shfl_xor_sync(F, oz, st);
                ow += __shfl_xor_sync(F, ow, st);
            }
            // lane cc (cc=0..3) holds fully-reduced o chunk cc

            if (hop == 0) {
                float o[16];
                #pragma unroll
                for (int cc = 0; cc < 4; cc++) {
                    o[4*cc+0] = __shfl_sync(F, ox, cc);
                    o[4*cc+1] = __shfl_sync(F, oy, cc);
                    o[4*cc+2] = __shfl_sync(F, oz, cc);
                    o[4*cc+3] = __shfl_sync(F, ow, cc);
                }
                res = 2.f * o[myd];
                const float* wr = shW + myd * WPAD;
                float nd = 0.f;
                #pragma unroll
                for (int e = 0; e < 16; e++) nd = fmaf(it[e] + o[e], wr[e], nd);
                #pragma unroll
                for (int e = 0; e < 16; e++) it[e] = __shfl_sync(F, nd, e);
            } else {
                const int src = myd >> 2;
                float t0 = __shfl_sync(F, ox, src);
                float t1 = __shfl_sync(F, oy, src);
                float t2 = __shfl_sync(F, oz, src);
                float t3 = __shfl_sync(F, ow, src);
                const int comp = myd & 3;
                res += (comp == 0) ? t0 : (comp == 1) ? t1 : (comp == 2) ? t2 : t3;
            }
        }

        if (lane < 16) out[n * DIM + lane] = res;
    }
}

extern "C" void kernel_launch(void* const* d_in, const int* in_sizes, int n_in,
                              void* d_out, int out_size)
{
    const int*   nodes = (const int*)  d_in[0];
    const int*   mh    = (const int*)  d_in[1];
    const int*   mr    = (const int*)  d_in[2];
    const int*   mt    = (const int*)  d_in[3];
    const float* ent   = (const float*)d_in[4];
    const float* rel   = (const float*)d_in[5];
    const float* W     = (const float*)d_in[6];
    float*       out   = (float*)      d_out;

    const int smem = R_WORDS * 4 + 16 * WPAD * 4;   // 32768 + 1088 B
    cudaFuncSetAttribute(ripple_kernel, cudaFuncAttributeMaxDynamicSharedMemorySize, smem);

    ripple_kernel<<<148 * 3, 256, smem>>>(nodes, mh, mr, mt, ent, rel, W, out);
}

// round 12
// speedup vs baseline: 2.3441x; 1.0361x over previous
#include <cuda_runtime.h>
#include <cuda_fp16.h>

#define NN   16384
#define NM   32
#define DIM  16
#define NR   64
#define WPAD 17      // 17*d mod 32 distinct for d=0..15 -> conflict-free W rows

// Shared layout: [0, 8192) uint32 words = fp16 R table (64 rel x 256 halves, identity order)
//                then W padded rows (16 x 17 floats)
#define R_WORDS (NR * 128)

__global__ __launch_bounds__(256, 3)
void ripple_kernel(const int*   __restrict__ nodes,
                   const int*   __restrict__ mh,
                   const int*   __restrict__ mr,
                   const int*   __restrict__ mt,
                   const float* __restrict__ ent,
                   const float* __restrict__ rel,
                   const float* __restrict__ W,
                   float*       __restrict__ out)
{
    extern __shared__ unsigned int shm[];
    float* shW = reinterpret_cast<float*>(shm + R_WORDS);

    // Stage R as fp16 (identity layout: half index = rid*256 + d*16 + e)
    {
        const float4* rel4 = reinterpret_cast<const float4*>(rel);
        for (int i = threadIdx.x; i < NR * 64; i += blockDim.x) {
            float4 v = rel4[i];
            __half2 a = __floats2half2_rn(v.x, v.y);
            __half2 b = __floats2half2_rn(v.z, v.w);
            shm[2*i]   = *reinterpret_cast<unsigned int*>(&a);
            shm[2*i+1] = *reinterpret_cast<unsigned int*>(&b);
        }
    }
    for (int i = threadIdx.x; i < 256; i += blockDim.x)
        shW[(i >> 4) * WPAD + (i & 15)] = W[i];
    __syncthreads();

    const unsigned F = 0xffffffffu;
    const int lane = threadIdx.x & 31;
    const int gw   = (blockIdx.x * blockDim.x + threadIdx.x) >> 5;
    const int nw   = (gridDim.x * blockDim.x) >> 5;
    const int g    = lane >> 3;        // octet id (0..3)
    const int k    = lane & 7;         // position within octet
    const int kh   = k & 1;            // which e-half of h this lane consumes (scores)
    const int kc   = k & 3;            // t chunk this lane accumulates
    const int khalf= k >> 2;           // r-range half for tail accumulation (0/1)
    const int k2   = k >> 1;           // d-offset selector (0..3)
    const int myd  = lane & 15;

    const float4* ent4 = reinterpret_cast<const float4*>(ent);
    const uint4*  shR4 = reinterpret_cast<const uint4*>(shm);

    for (int n = gw; n < NN; n += nw) {
        float it[16];
        {
            const float4* p = ent4 + (size_t)__ldg(nodes + n) * 4;
            #pragma unroll
            for (int j = 0; j < 4; j++) {
                float4 v = __ldg(p + j);
                it[4*j+0] = v.x; it[4*j+1] = v.y; it[4*j+2] = v.z; it[4*j+3] = v.w;
            }
        }

        float res = 0.f;

        #pragma unroll
        for (int hop = 0; hop < 2; hop++) {
            const int sbase = (hop * NN + n) * NM;

            // item value this lane needs per j: it[4j + k2]
            float itp[4];
            #pragma unroll
            for (int j = 0; j < 4; j++) {
                itp[j] = (k2 == 0) ? it[4*j] : (k2 == 1) ? it[4*j+1]
                       : (k2 == 2) ? it[4*j+2] : it[4*j+3];
            }

            // ---- scores: octet g handles slot m = 4r+g; R reads conflict-free ----
            float s[8];
            #pragma unroll
            for (int r = 0; r < 8; r++) {
                const int m   = 4 * r + g;
                const int hid = __ldg(mh + sbase + m);        // octet-uniform
                const int rid = __ldg(mr + sbase + m);
                float4 ha = __ldg(ent4 + (size_t)hid * 4 + 2 * kh);
                float4 hb = __ldg(ent4 + (size_t)hid * 4 + 2 * kh + 1);
                __half2 h2_0 = __floats2half2_rn(ha.x, ha.y);
                __half2 h2_1 = __floats2half2_rn(ha.z, ha.w);
                __half2 h2_2 = __floats2half2_rn(hb.x, hb.y);
                __half2 h2_3 = __floats2half2_rn(hb.z, hb.w);

                const uint4* rb = shR4 + rid * 32 + k;        // word rid*128 + 4k
                float sp = 0.f;
                #pragma unroll
                for (int j = 0; j < 4; j++) {                 // d = 4j + k2
                    uint4 w = rb[8 * j];                      // banks 4k..4k+3: conflict-free
                    __half2 acc = __hmul2(*reinterpret_cast<__half2*>(&w.x), h2_0);
                    acc = __hfma2(*reinterpret_cast<__half2*>(&w.y), h2_1, acc);
                    acc = __hfma2(*reinterpret_cast<__half2*>(&w.z), h2_2, acc);
                    acc = __hfma2(*reinterpret_cast<__half2*>(&w.w), h2_3, acc);
                    float2 f = __half22float2(acc);
                    sp = fmaf(itp[j], f.x + f.y, sp);
                }
                sp += __shfl_xor_sync(F, sp, 1);
                sp += __shfl_xor_sync(F, sp, 2);
                sp += __shfl_xor_sync(F, sp, 4);
                s[r] = sp;                                    // score of slot 4r+g
            }

            // ---- softmax over 32 slots (8 local + butterfly across octets) ----
            float p[8];
            {
                float mx = s[0];
                #pragma unroll
                for (int r = 1; r < 8; r++) mx = fmaxf(mx, s[r]);
                mx = fmaxf(mx, __shfl_xor_sync(F, mx, 8));
                mx = fmaxf(mx, __shfl_xor_sync(F, mx, 16));
                float ls = 0.f;
                #pragma unroll
                for (int r = 0; r < 8; r++) { p[r] = __expf(s[r] - mx); ls += p[r]; }
                ls += __shfl_xor_sync(F, ls, 8);
                ls += __shfl_xor_sync(F, ls, 16);
                float inv = 1.f / ls;
                #pragma unroll
                for (int r = 0; r < 8; r++) p[r] *= inv;
            }

            // ---- o = sum p_m * t_m ----
            // Lane handles chunk kc of slots r in its half (khalf): r = 4*khalf + rr.
            float ox = 0.f, oy = 0.f, oz = 0.f, ow = 0.f;
            #pragma unroll
            for (int rr = 0; rr < 4; rr++) {
                const int r   = 4 * khalf + rr;
                const int tid = __ldg(mt + sbase + 4 * r + g);
                float4 tv = __ldg(ent4 + (size_t)tid * 4 + kc);
                ox = fmaf(p[r], tv.x, ox); oy = fmaf(p[r], tv.y, oy);
                oz = fmaf(p[r], tv.z, oz); ow = fmaf(p[r], tv.w, ow);
            }
            #pragma unroll
            for (int st = 4; st <= 16; st <<= 1) {
                ox += __shfl_xor_sync(F, ox, st);
                oy += __shfl_xor_sync(F, oy, st);
                oz += __shfl_xor_sync(F, oz, st);
                ow += __shfl_xor_sync(F, ow, st);
            }
            // lane cc (cc=0..3) holds fully-reduced o chunk cc

            if (hop == 0) {
                float o[16];
                #pragma unroll
                for (int cc = 0; cc < 4; cc++) {
                    o[4*cc+0] = __shfl_sync(F, ox, cc);
                    o[4*cc+1] = __shfl_sync(F, oy, cc);
                    o[4*cc+2] = __shfl_sync(F, oz, cc);
                    o[4*cc+3] = __shfl_sync(F, ow, cc);
                }
                res = 2.f * o[myd];
                const float* wr = shW + myd * WPAD;
                float nd = 0.f;
                #pragma unroll
                for (int e = 0; e < 16; e++) nd = fmaf(it[e] + o[e], wr[e], nd);
                #pragma unroll
                for (int e = 0; e < 16; e++) it[e] = __shfl_sync(F, nd, e);
            } else {
                const int src = myd >> 2;
                float t0 = __shfl_sync(F, ox, src);
                float t1 = __shfl_sync(F, oy, src);
                float t2 = __shfl_sync(F, oz, src);
                float t3 = __shfl_sync(F, ow, src);
                const int comp = myd & 3;
                res += (comp == 0) ? t0 : (comp == 1) ? t1 : (comp == 2) ? t2 : t3;
            }
        }

        if (lane < 16) out[n * DIM + lane] = res;
    }
}

extern "C" void kernel_launch(void* const* d_in, const int* in_sizes, int n_in,
                              void* d_out, int out_size)
{
    const int*   nodes = (const int*)  d_in[0];
    const int*   mh    = (const int*)  d_in[1];
    const int*   mr    = (const int*)  d_in[2];
    const int*   mt    = (const int*)  d_in[3];
    const float* ent   = (const float*)d_in[4];
    const float* rel   = (const float*)d_in[5];
    const float* W     = (const float*)d_in[6];
    float*       out   = (float*)      d_out;

    const int smem = R_WORDS * 4 + 16 * WPAD * 4;   // 32768 + 1088 B
    cudaFuncSetAttribute(ripple_kernel, cudaFuncAttributeMaxDynamicSharedMemorySize, smem);

    ripple_kernel<<<148 * 3, 256, smem>>>(nodes, mh, mr, mt, ent, rel, W, out);
}

// round 14
// speedup vs baseline: 2.3639x; 1.0084x over previous
#include <cuda_runtime.h>
#include <cuda_fp16.h>

#define NE   100000
#define NN   16384
#define NM   32
#define DIM  16
#define NR   64
#define WPAD 17      // 17*d mod 32 distinct for d=0..15 -> conflict-free W rows

#define R_WORDS (NR * 128)   // fp16 R table: 64 rel x 256 halves = 8192 uint32 words

// fp16 mirror of entity_emb: ent_h2[id*8 + j] = (ent[id*16+2j], ent[id*16+2j+1])
__device__ __half2 g_ent[NE * 8];

__global__ void k_cvt(const float2* __restrict__ ent2) {
    int i = blockIdx.x * blockDim.x + threadIdx.x;
    if (i < NE * 8) {
        float2 v = __ldg(ent2 + i);
        g_ent[i] = __floats2half2_rn(v.x, v.y);
    }
}

__global__ __launch_bounds__(256, 3)
void ripple_kernel(const int*   __restrict__ nodes,
                   const int*   __restrict__ mh,
                   const int*   __restrict__ mr,
                   const int*   __restrict__ mt,
                   const float* __restrict__ ent,
                   const float* __restrict__ rel,
                   const float* __restrict__ W,
                   float*       __restrict__ out)
{
    extern __shared__ unsigned int shm[];
    float* shW = reinterpret_cast<float*>(shm + R_WORDS);

    // Stage R as fp16 (identity layout: half index = rid*256 + d*16 + e)
    {
        const float4* rel4 = reinterpret_cast<const float4*>(rel);
        for (int i = threadIdx.x; i < NR * 64; i += blockDim.x) {
            float4 v = rel4[i];
            __half2 a = __floats2half2_rn(v.x, v.y);
            __half2 b = __floats2half2_rn(v.z, v.w);
            shm[2*i]   = *reinterpret_cast<unsigned int*>(&a);
            shm[2*i+1] = *reinterpret_cast<unsigned int*>(&b);
        }
    }
    for (int i = threadIdx.x; i < 256; i += blockDim.x)
        shW[(i >> 4) * WPAD + (i & 15)] = W[i];
    __syncthreads();

    const unsigned F = 0xffffffffu;
    const int lane = threadIdx.x & 31;
    const int gw   = (blockIdx.x * blockDim.x + threadIdx.x) >> 5;
    const int nw   = (gridDim.x * blockDim.x) >> 5;
    const int g    = lane >> 3;        // octet id (0..3)
    const int k    = lane & 7;         // position within octet
    const int kh   = k & 1;            // which e-half of h this lane consumes (scores)
    const int kc   = k & 3;            // t chunk this lane accumulates
    const int khalf= k >> 2;           // r-range half for tail accumulation (0/1)
    const int k2   = k >> 1;           // d-offset selector (0..3)
    const int myd  = lane & 15;

    const float4* ent4  = reinterpret_cast<const float4*>(ent);
    const uint4*  shR4  = reinterpret_cast<const uint4*>(shm);
    const uint4*  entH4 = reinterpret_cast<const uint4*>(g_ent);   // 16B = one e-half
    const uint2*  entH2 = reinterpret_cast<const uint2*>(g_ent);   // 8B  = one t chunk

    for (int n = gw; n < NN; n += nw) {
        float it[16];
        {
            const float4* p = ent4 + (size_t)__ldg(nodes + n) * 4;
            #pragma unroll
            for (int j = 0; j < 4; j++) {
                float4 v = __ldg(p + j);
                it[4*j+0] = v.x; it[4*j+1] = v.y; it[4*j+2] = v.z; it[4*j+3] = v.w;
            }
        }

        float res = 0.f;

        #pragma unroll
        for (int hop = 0; hop < 2; hop++) {
            const int sbase = (hop * NN + n) * NM;

            // item value this lane needs per j: it[4j + k2]
            float itp[4];
            #pragma unroll
            for (int j = 0; j < 4; j++) {
                itp[j] = (k2 == 0) ? it[4*j] : (k2 == 1) ? it[4*j+1]
                       : (k2 == 2) ? it[4*j+2] : it[4*j+3];
            }

            // ---- scores: octet g handles slot m = 4r+g; R reads conflict-free ----
            float s[8];
            #pragma unroll
            for (int r = 0; r < 8; r++) {
                const int m   = 4 * r + g;
                const int hid = __ldg(mh + sbase + m);        // octet-uniform
                const int rid = __ldg(mr + sbase + m);
                // lane's e-half of h, fp16, already half2-paired: 16B
                uint4 hw = __ldg(entH4 + (size_t)hid * 2 + kh);
                __half2 h2_0 = *reinterpret_cast<__half2*>(&hw.x);
                __half2 h2_1 = *reinterpret_cast<__half2*>(&hw.y);
                __half2 h2_2 = *reinterpret_cast<__half2*>(&hw.z);
                __half2 h2_3 = *reinterpret_cast<__half2*>(&hw.w);

                const uint4* rb = shR4 + rid * 32 + k;        // word rid*128 + 4k
                float sp = 0.f;
                #pragma unroll
                for (int j = 0; j < 4; j++) {                 // d = 4j + k2
                    uint4 w = rb[8 * j];                      // banks 4k..4k+3: conflict-free
                    __half2 acc = __hmul2(*reinterpret_cast<__half2*>(&w.x), h2_0);
                    acc = __hfma2(*reinterpret_cast<__half2*>(&w.y), h2_1, acc);
                    acc = __hfma2(*reinterpret_cast<__half2*>(&w.z), h2_2, acc);
                    acc = __hfma2(*reinterpret_cast<__half2*>(&w.w), h2_3, acc);
                    float2 f = __half22float2(acc);
                    sp = fmaf(itp[j], f.x + f.y, sp);
                }
                sp += __shfl_xor_sync(F, sp, 1);
                sp += __shfl_xor_sync(F, sp, 2);
                sp += __shfl_xor_sync(F, sp, 4);
                s[r] = sp;                                    // score of slot 4r+g
            }

            // ---- softmax over 32 slots (8 local + butterfly across octets) ----
            float p[8];
            {
                float mx = s[0];
                #pragma unroll
                for (int r = 1; r < 8; r++) mx = fmaxf(mx, s[r]);
                mx = fmaxf(mx, __shfl_xor_sync(F, mx, 8));
                mx = fmaxf(mx, __shfl_xor_sync(F, mx, 16));
                float ls = 0.f;
                #pragma unroll
                for (int r = 0; r < 8; r++) { p[r] = __expf(s[r] - mx); ls += p[r]; }
                ls += __shfl_xor_sync(F, ls, 8);
                ls += __shfl_xor_sync(F, ls, 16);
                float inv = 1.f / ls;
                #pragma unroll
                for (int r = 0; r < 8; r++) p[r] *= inv;
            }

            // ---- o = sum p_m * t_m (fp16 t chunks, fp32 accumulate) ----
            float ox = 0.f, oy = 0.f, oz = 0.f, ow = 0.f;
            #pragma unroll
            for (int rr = 0; rr < 4; rr++) {
                const int r   = 4 * khalf + rr;
                const int tid = __ldg(mt + sbase + 4 * r + g);
                uint2 tw = __ldg(entH2 + (size_t)tid * 4 + kc);   // chunk kc: 8B
                float2 ta = __half22float2(*reinterpret_cast<__half2*>(&tw.x));
                float2 tb = __half22float2(*reinterpret_cast<__half2*>(&tw.y));
                ox = fmaf(p[r], ta.x, ox); oy = fmaf(p[r], ta.y, oy);
                oz = fmaf(p[r], tb.x, oz); ow = fmaf(p[r], tb.y, ow);
            }
            #pragma unroll
            for (int st = 4; st <= 16; st <<= 1) {
                ox += __shfl_xor_sync(F, ox, st);
                oy += __shfl_xor_sync(F, oy, st);
                oz += __shfl_xor_sync(F, oz, st);
                ow += __shfl_xor_sync(F, ow, st);
            }
            // lane cc (cc=0..3) holds fully-reduced o chunk cc

            if (hop == 0) {
                float o[16];
                #pragma unroll
                for (int cc = 0; cc < 4; cc++) {
                    o[4*cc+0] = __shfl_sync(F, ox, cc);
                    o[4*cc+1] = __shfl_sync(F, oy, cc);
                    o[4*cc+2] = __shfl_sync(F, oz, cc);
                    o[4*cc+3] = __shfl_sync(F, ow, cc);
                }
                res = 2.f * o[myd];
                const float* wr = shW + myd * WPAD;
                float nd = 0.f;
                #pragma unroll
                for (int e = 0; e < 16; e++) nd = fmaf(it[e] + o[e], wr[e], nd);
                #pragma unroll
                for (int e = 0; e < 16; e++) it[e] = __shfl_sync(F, nd, e);
            } else {
                const int src = myd >> 2;
                float t0 = __shfl_sync(F, ox, src);
                float t1 = __shfl_sync(F, oy, src);
                float t2 = __shfl_sync(F, oz, src);
                float t3 = __shfl_sync(F, ow, src);
                const int comp = myd & 3;
                res += (comp == 0) ? t0 : (comp == 1) ? t1 : (comp == 2) ? t2 : t3;
            }
        }

        if (lane < 16) out[n * DIM + lane] = res;
    }
}

extern "C" void kernel_launch(void* const* d_in, const int* in_sizes, int n_in,
                              void* d_out, int out_size)
{
    const int*   nodes = (const int*)  d_in[0];
    const int*   mh    = (const int*)  d_in[1];
    const int*   mr    = (const int*)  d_in[2];
    const int*   mt    = (const int*)  d_in[3];
    const float* ent   = (const float*)d_in[4];
    const float* rel   = (const float*)d_in[5];
    const float* W     = (const float*)d_in[6];
    float*       out   = (float*)      d_out;

    // Build fp16 entity mirror (graph-capturable, deterministic)
    k_cvt<<<(NE * 8 + 255) / 256, 256>>>(reinterpret_cast<const float2*>(ent));

    const int smem = R_WORDS * 4 + 16 * WPAD * 4;   // 32768 + 1088 B
    cudaFuncSetAttribute(ripple_kernel, cudaFuncAttributeMaxDynamicSharedMemorySize, smem);

    ripple_kernel<<<148 * 3, 256, smem>>>(nodes, mh, mr, mt, ent, rel, W, out);
}

// round 15
// speedup vs baseline: 2.5548x; 1.0808x over previous
#include <cuda_runtime.h>
#include <cuda_fp16.h>

#define NE   100000
#define NN   16384
#define NM   32
#define NR   64
#define WPAD 20      // 16B-aligned W rows; d=0..7 start-banks cover all 32

#define R_WORDS (NR * 128)   // fp16 R table: 64 rel x 256 halves

__device__ __half2 g_ent[NE * 8];

__global__ void k_cvt(const float2* __restrict__ ent2) {
    int i = blockIdx.x * blockDim.x + threadIdx.x;
    if (i < NE * 8) {
        float2 v = __ldg(ent2 + i);
        g_ent[i] = __floats2half2_rn(v.x, v.y);
    }
}

static __device__ __forceinline__ __half2 h2c(unsigned int u) {
    return *reinterpret_cast<__half2*>(&u);
}

__global__ __launch_bounds__(256, 4)
void ripple_kernel(const int*   __restrict__ nodes,
                   const int*   __restrict__ mh,
                   const int*   __restrict__ mr,
                   const int*   __restrict__ mt,
                   const float* __restrict__ ent,
                   const float* __restrict__ rel,
                   const float* __restrict__ W,
                   float*       __restrict__ out)
{
    extern __shared__ unsigned int shm[];
    float* shW = reinterpret_cast<float*>(shm + R_WORDS);

    // Stage R as fp16 (identity layout: half index = rid*256 + d*16 + e)
    {
        const float4* rel4 = reinterpret_cast<const float4*>(rel);
        for (int i = threadIdx.x; i < NR * 64; i += blockDim.x) {
            float4 v = rel4[i];
            __half2 a = __floats2half2_rn(v.x, v.y);
            __half2 b = __floats2half2_rn(v.z, v.w);
            shm[2*i]   = *reinterpret_cast<unsigned int*>(&a);
            shm[2*i+1] = *reinterpret_cast<unsigned int*>(&b);
        }
    }
    for (int i = threadIdx.x; i < 256; i += blockDim.x)
        shW[(i >> 4) * WPAD + (i & 15)] = W[i];
    __syncthreads();

    const unsigned F = 0xffffffffu;
    const int lane  = threadIdx.x & 31;
    const int gw    = (blockIdx.x * blockDim.x + threadIdx.x) >> 5;
    const int nw    = (gridDim.x * blockDim.x) >> 5;
    const int g     = lane >> 3;        // octet id (0..3)
    const int k     = lane & 7;         // position within octet
    const int kh    = k & 1;            // e-half of h for scores
    const int kc    = k & 3;            // t chunk accumulated
    const int khalf = k >> 2;           // r-range half (0/1)
    const int k2    = (k >> 1) & 3;     // d-offset selector
    const int myd   = lane & 15;

    const float4* ent4  = reinterpret_cast<const float4*>(ent);
    const uint4*  shR4  = reinterpret_cast<const uint4*>(shm);
    const uint4*  entH4 = reinterpret_cast<const uint4*>(g_ent);
    const uint2*  entH2 = reinterpret_cast<const uint2*>(g_ent);

    for (int n = gw; n < NN; n += nw) {
        // item row pointer (uniform, L1-hot); keep only the 4 elements scores need
        const float4* itrow = ent4 + (size_t)__ldg(nodes + n) * 4;
        float itp[4];
        #pragma unroll
        for (int j = 0; j < 4; j++) {
            float4 v = __ldg(itrow + j);
            itp[j] = (k2 == 0) ? v.x : (k2 == 1) ? v.y : (k2 == 2) ? v.z : v.w;
        }

        float res = 0.f;

        #pragma unroll
        for (int hop = 0; hop < 2; hop++) {
            const int sbase = (hop * NN + n) * NM;

            // ---- score partials: a[r] = this lane's partial for slot 4r+g ----
            float a[8];
            #pragma unroll
            for (int r = 0; r < 8; r++) {
                const int m   = 4 * r + g;
                const int hid = __ldg(mh + sbase + m);
                const int rid = __ldg(mr + sbase + m);
                uint4 hw = __ldg(entH4 + (size_t)hid * 2 + kh);
                __half2 h0 = h2c(hw.x), h1 = h2c(hw.y), h2v = h2c(hw.z), h3 = h2c(hw.w);

                const uint4* rb = shR4 + rid * 32 + k;       // conflict-free
                float sp = 0.f;
                #pragma unroll
                for (int j = 0; j < 4; j++) {                // d = 4j + k2
                    uint4 w = rb[8 * j];
                    __half2 acc = __hmul2(h2c(w.x), h0);
                    acc = __hfma2(h2c(w.y), h1, acc);
                    acc = __hfma2(h2c(w.z), h2v, acc);
                    acc = __hfma2(h2c(w.w), h3, acc);
                    float2 f = __half22float2(acc);
                    sp = fmaf(itp[j], f.x + f.y, sp);
                }
                a[r] = sp;
            }

            // ---- octet vector butterfly (7 shfl): lane 8g+k gets score of slot 4k+g ----
            float s;
            {
                float c[4];
                #pragma unroll
                for (int j = 0; j < 4; j++) {
                    float sent = khalf ? a[j] : a[j + 4];
                    float recv = __shfl_xor_sync(F, sent, 4);
                    c[j] = (khalf ? a[j + 4] : a[j]) + recv;
                }
                const int b1 = (k >> 1) & 1;
                float d0, d1;
                {
                    float sent = b1 ? c[0] : c[2];
                    float recv = __shfl_xor_sync(F, sent, 2);
                    d0 = (b1 ? c[2] : c[0]) + recv;
                }
                {
                    float sent = b1 ? c[1] : c[3];
                    float recv = __shfl_xor_sync(F, sent, 2);
                    d1 = (b1 ? c[3] : c[1]) + recv;
                }
                const int b0 = k & 1;
                float sent = b0 ? d0 : d1;
                float recv = __shfl_xor_sync(F, sent, 1);
                s = (b0 ? d1 : d0) + recv;
            }

            // ---- softmax: scalar per lane (1 exp), full-warp butterflies ----
            float mx = s;
            #pragma unroll
            for (int st = 1; st <= 16; st <<= 1)
                mx = fmaxf(mx, __shfl_xor_sync(F, mx, st));
            float ev = __expf(s - mx);
            float sum = ev;
            #pragma unroll
            for (int st = 1; st <= 16; st <<= 1)
                sum += __shfl_xor_sync(F, sum, st);
            float pown = ev / sum;                 // p of slot 4k+g

            // weights for this lane's tail slots (r' = 4*khalf+rr, lives on lane 8g+r')
            float pw[4];
            #pragma unroll
            for (int rr = 0; rr < 4; rr++)
                pw[rr] = __shfl_sync(F, pown, (lane & 24) + 4 * khalf + rr);

            // ---- o = sum p_m * t_m (fp16 t chunks, fp32 accumulate) ----
            float ox = 0.f, oy = 0.f, oz = 0.f, ow = 0.f;
            #pragma unroll
            for (int rr = 0; rr < 4; rr++) {
                const int r   = 4 * khalf + rr;
                const int tid = __ldg(mt + sbase + 4 * r + g);
                uint2 tw = __ldg(entH2 + (size_t)tid * 4 + kc);
                float2 ta = __half22float2(h2c(tw.x));
                float2 tb = __half22float2(h2c(tw.y));
                ox = fmaf(pw[rr], ta.x, ox); oy = fmaf(pw[rr], ta.y, oy);
                oz = fmaf(pw[rr], tb.x, oz); ow = fmaf(pw[rr], tb.y, ow);
            }
            #pragma unroll
            for (int st = 4; st <= 16; st <<= 1) {
                ox += __shfl_xor_sync(F, ox, st);
                oy += __shfl_xor_sync(F, oy, st);
                oz += __shfl_xor_sync(F, oz, st);
                ow += __shfl_xor_sync(F, ow, st);
            }
            // lane cc holds fully-reduced o chunk cc

            if (hop == 0) {
                // nd = sum_e (item[e]+o[e])*W[myd][e], item re-loaded (uniform L1 hits)
                float nd = 0.f, omyd = 0.f;
                const float* wr = shW + myd * WPAD;
                const int mycc = myd >> 2, mycomp = myd & 3;
                #pragma unroll
                for (int cc = 0; cc < 4; cc++) {
                    float o0 = __shfl_sync(F, ox, cc);
                    float o1 = __shfl_sync(F, oy, cc);
                    float o2 = __shfl_sync(F, oz, cc);
                    float o3 = __shfl_sync(F, ow, cc);
                    float4 iv = __ldg(itrow + cc);
                    float4 wv = *reinterpret_cast<const float4*>(wr + 4 * cc);
                    nd = fmaf(iv.x + o0, wv.x, nd);
                    nd = fmaf(iv.y + o1, wv.y, nd);
                    nd = fmaf(iv.z + o2, wv.z, nd);
                    nd = fmaf(iv.w + o3, wv.w, nd);
                    if (cc == mycc)
                        omyd = (mycomp == 0) ? o0 : (mycomp == 1) ? o1
                             : (mycomp == 2) ? o2 : o3;
                }
                res = 2.f * omyd;
                // itp for hop 1 from the updated item (nd on lanes 0..15)
                #pragma unroll
                for (int j = 0; j < 4; j++)
                    itp[j] = __shfl_sync(F, nd, 4 * j + k2);
            } else {
                const int src = myd >> 2;
                float t0 = __shfl_sync(F, ox, src);
                float t1 = __shfl_sync(F, oy, src);
                float t2 = __shfl_sync(F, oz, src);
                float t3 = __shfl_sync(F, ow, src);
                const int comp = myd & 3;
                res += (comp == 0) ? t0 : (comp == 1) ? t1 : (comp == 2) ? t2 : t3;
            }
        }

        if (lane < 16) out[n * 16 + lane] = res;
    }
}

extern "C" void kernel_launch(void* const* d_in, const int* in_sizes, int n_in,
                              void* d_out, int out_size)
{
    const int*   nodes = (const int*)  d_in[0];
    const int*   mh    = (const int*)  d_in[1];
    const int*   mr    = (const int*)  d_in[2];
    const int*   mt    = (const int*)  d_in[3];
    const float* ent   = (const float*)d_in[4];
    const float* rel   = (const float*)d_in[5];
    const float* W     = (const float*)d_in[6];
    float*       out   = (float*)      d_out;

    k_cvt<<<(NE * 8 + 255) / 256, 256>>>(reinterpret_cast<const float2*>(ent));

    const int smem = R_WORDS * 4 + 16 * WPAD * 4;   // 32768 + 1280 B
    cudaFuncSetAttribute(ripple_kernel, cudaFuncAttributeMaxDynamicSharedMemorySize, smem);

    ripple_kernel<<<148 * 4, 256, smem>>>(nodes, mh, mr, mt, ent, rel, W, out);
}